// round 1
// baseline (speedup 1.0000x reference)
#include <cuda_runtime.h>
#include <cmath>

#define Bb 1024
#define Ll 128
#define Ww 512
#define Ss 8
#define NSTEPS 12
#define NLABEL 10

// ---------------- scratch (static device globals; no allocations) ----------
static __device__ float g_cat[Bb*3*Ww];
static __device__ float g_summary[Bb*Ww];
static __device__ float g_shared[Bb*2*Ww];   // [h | summary]
static __device__ float g_h[Bb*Ww];
static __device__ float g_hsA[Ss*Bb*Ww];
static __device__ float g_hsB[Ss*Bb*Ww];
static __device__ float g_f0[Ss*Bb*Ww];      // f0, later reused as prism feat2
static __device__ float g_feats[Ss*Bb*Ww];
static __device__ float g_gi[Ss*Bb*3*Ww];
static __device__ float g_gh[Ss*Bb*3*Ww];
static __device__ float g_upd[Ss*Bb*Ww];
static __device__ float g_gate[Ss*Bb];

__device__ __forceinline__ float sigf(float x) { return 1.f/(1.f + expf(-x)); }

// ---------------- generic batched SGEMM: C = act(A*Bt^T + bias + D)*gate*scale
// A: [M,K] row-major (lda), Bt: [N,K] row-major (ldb) -> C[M,N] (ldc)
// batched over blockIdx.z with per-operand batch strides; aRot shifts the A
// batch index by -1 mod gridDim.z (the sparse ring "roll").
struct GemmArgs {
    const float* A; const float* Bt; const float* bias; const float* D; const float* gate;
    float* C;
    int lda, ldb, ldd, ldc;
    long long aBatch, bBatch, biasBatch, dBatch, cBatch;
    int K, aRot, act;    // act: 0=none, 1=tanh
    float scale;
};

__global__ __launch_bounds__(256, 2) void sgemm(GemmArgs g) {
    int z  = blockIdx.z;
    int nz = gridDim.z;
    int az = g.aRot ? (z + nz - 1) % nz : z;
    const float* A  = g.A  + (long long)az * g.aBatch;
    const float* Bt = g.Bt + (long long)z  * g.bBatch;
    float* C = g.C + (long long)z * g.cBatch;
    int m0 = blockIdx.y * 128, n0 = blockIdx.x * 128;

    __shared__ float As[2][8][128];
    __shared__ float Bs[2][8][128];

    int tid = threadIdx.x;
    int lm = tid >> 1;
    int lk = (tid & 1) << 2;
    const float* aptr = A  + (long long)(m0 + lm) * g.lda + lk;
    const float* bptr = Bt + (long long)(n0 + lm) * g.ldb + lk;

    float4 pa = *(const float4*)aptr;
    float4 pb = *(const float4*)bptr;
    As[0][lk+0][lm]=pa.x; As[0][lk+1][lm]=pa.y; As[0][lk+2][lm]=pa.z; As[0][lk+3][lm]=pa.w;
    Bs[0][lk+0][lm]=pb.x; Bs[0][lk+1][lm]=pb.y; Bs[0][lk+2][lm]=pb.z; Bs[0][lk+3][lm]=pb.w;
    __syncthreads();

    float acc[8][8];
#pragma unroll
    for (int i=0;i<8;i++)
#pragma unroll
        for (int j=0;j<8;j++) acc[i][j]=0.f;

    int tx = tid & 15, ty = tid >> 4;
    int nkt = g.K >> 3;

    for (int kt=0; kt<nkt; ++kt) {
        int cur = kt & 1;
        if (kt+1 < nkt) {
            pa = *(const float4*)(aptr + (kt+1)*8);
            pb = *(const float4*)(bptr + (kt+1)*8);
        }
#pragma unroll
        for (int k=0;k<8;k++) {
            float4 a0 = *(const float4*)&As[cur][k][ty*8];
            float4 a1 = *(const float4*)&As[cur][k][ty*8+4];
            float4 b0 = *(const float4*)&Bs[cur][k][tx*8];
            float4 b1 = *(const float4*)&Bs[cur][k][tx*8+4];
            float av[8]={a0.x,a0.y,a0.z,a0.w,a1.x,a1.y,a1.z,a1.w};
            float bv[8]={b0.x,b0.y,b0.z,b0.w,b1.x,b1.y,b1.z,b1.w};
#pragma unroll
            for (int i=0;i<8;i++)
#pragma unroll
                for (int j=0;j<8;j++) acc[i][j] = fmaf(av[i], bv[j], acc[i][j]);
        }
        if (kt+1 < nkt) {
            int nx = cur ^ 1;
            As[nx][lk+0][lm]=pa.x; As[nx][lk+1][lm]=pa.y; As[nx][lk+2][lm]=pa.z; As[nx][lk+3][lm]=pa.w;
            Bs[nx][lk+0][lm]=pb.x; Bs[nx][lk+1][lm]=pb.y; Bs[nx][lk+2][lm]=pb.z; Bs[nx][lk+3][lm]=pb.w;
            __syncthreads();
        }
    }

    const float* bias = g.bias ? g.bias + (long long)z*g.biasBatch : nullptr;
    const float* D    = g.D    ? g.D    + (long long)z*g.dBatch    : nullptr;
    int M = gridDim.y * 128;
#pragma unroll
    for (int i=0;i<8;i++) {
        int m = m0 + ty*8 + i;
        float gm = g.gate ? g.gate[(long long)z*M + m] : 1.f;
#pragma unroll
        for (int j=0;j<8;j++) {
            int n = n0 + tx*8 + j;
            float v = acc[i][j];
            if (bias) v += bias[n];
            if (D)    v += D[(long long)m*g.ldd + n];
            if (g.act) v = tanhf(v);
            v *= gm * g.scale;
            C[(long long)m*g.ldc + n] = v;
        }
    }
}

// ---------------- encode: masked mean / masked max / "last" (emb[count-1]) --
__global__ void encode_kernel(const int* __restrict__ x, const float* __restrict__ embed) {
    int b = blockIdx.x;
    int t = threadIdx.x;  // 128
    __shared__ int sx[Ll];
    sx[t] = x[b*Ll + t];
    __syncthreads();
    float sm[4] = {0,0,0,0};
    float mx[4] = {-10000.f,-10000.f,-10000.f,-10000.f};
    int cnt = 0;
    for (int l=0; l<Ll; l++) {
        int tok = sx[l];
        if (tok != 0) {
            cnt++;
            const float* e = embed + tok*Ww;
#pragma unroll
            for (int q=0;q<4;q++) {
                float v = e[t + q*128];
                sm[q] += v;
                mx[q] = fmaxf(mx[q], v);
            }
        }
    }
    float denom = (float)(cnt > 0 ? cnt : 1);
    int li = cnt > 0 ? cnt - 1 : 0;
    const float* le = embed + sx[li]*Ww;
    float* cat = g_cat + (long long)b*3*Ww;
#pragma unroll
    for (int q=0;q<4;q++) {
        int w = t + q*128;
        cat[w]        = sm[q] / denom;
        cat[Ww + w]   = mx[q];               // -10000 is finite -> kept, matches ref
        cat[2*Ww + w] = le[w];
    }
}

__global__ void post_summary() {
    int i = blockIdx.x*256 + threadIdx.x;    // B*W
    float v = g_summary[i];
    g_h[i] = v;
    int b = i >> 9, w = i & 511;
    g_shared[b*1024 + w]       = v;          // h0 = summary
    g_shared[b*1024 + 512 + w] = v;          // summary half (constant)
}

__global__ void zero_kernel(float* p) {
    int i = blockIdx.x*256 + threadIdx.x;
    p[i] = 0.f;
}

// ---------------- GRU combine (torch gate order r,z,n) ----------------------
__global__ void gru_combine(const float* __restrict__ hsOld, float* __restrict__ hsNew) {
    int i = blockIdx.x*256 + threadIdx.x;    // S*B*W
    int w = i & 511;
    long long sb = (long long)(i >> 9);
    long long base = sb * 1536;
    float r  = sigf(g_gi[base + w]        + g_gh[base + w]);
    float zz = sigf(g_gi[base + 512 + w]  + g_gh[base + 512 + w]);
    float n  = tanhf(g_gi[base + 1024 + w] + r * g_gh[base + 1024 + w]);
    float old = hsOld[i];
    hsNew[i] = (1.f - zz)*n + zz*old;
}

// ---------------- gate dot + prismion feat2 ---------------------------------
__global__ void prism_gate(const float* __restrict__ hsNew,
                           const float* __restrict__ Wg, const float* __restrict__ bg,
                           const float* __restrict__ phase, const float* __restrict__ pgain) {
    int b = blockIdx.x, s = blockIdx.y;
    int t = threadIdx.x;  // 128
    const float* row = hsNew + ((long long)s*Bb + b)*Ww;
    float* f2 = g_f0 + ((long long)s*Bb + b)*Ww;   // reuse f0 buffer
    float dot = 0.f;
#pragma unroll
    for (int q=0;q<4;q++) {
        int w = t + q*128;
        float hv = row[w];
        dot += Wg[s*Ww + w] * hv;
        float c  = cosf(hv + phase[s*Ww + w]);
        float gx = pgain[s*Ww + w];
        float gn = gx > 20.f ? gx : log1pf(expf(gx));   // softplus
        f2[w] = c*c*gn;
    }
#pragma unroll
    for (int o=16;o;o>>=1) dot += __shfl_down_sync(0xffffffffu, dot, o);
    __shared__ float red[4];
    if ((t & 31) == 0) red[t>>5] = dot;
    __syncthreads();
    if (t == 0) {
        float d = red[0]+red[1]+red[2]+red[3];
        g_gate[s*Bb + b] = sigf(d + bg[s]);
    }
}

// ---------------- h update: tanh(h*decay + sum_s upd) -----------------------
__global__ void h_update(const float* __restrict__ decay_param) {
    int i = blockIdx.x*256 + threadIdx.x;    // B*W
    float dec = sigf(decay_param[0]);
    float acc = 0.f;
#pragma unroll
    for (int s=0;s<Ss;s++) acc += g_upd[(long long)s*Bb*Ww + i];  // scale folded in
    float hv = tanhf(g_h[i]*dec + acc);
    g_h[i] = hv;
    int b = i >> 9, w = i & 511;
    g_shared[b*1024 + w] = hv;
}

// ---------------- output projection [B,10] ----------------------------------
__global__ void out_proj(const float* __restrict__ Wout, const float* __restrict__ bout,
                         float* __restrict__ out) {
    int b = blockIdx.x;
    int j = threadIdx.y, lane = threadIdx.x;
    const float* hr = g_h + (long long)b*Ww;
    const float* wr = Wout + j*Ww;
    float acc = 0.f;
    for (int w=lane; w<Ww; w+=32) acc += hr[w]*wr[w];
#pragma unroll
    for (int o=16;o;o>>=1) acc += __shfl_down_sync(0xffffffffu, acc, o);
    if (lane == 0) out[b*NLABEL + j] = acc + bout[j];
}

// ---------------- host orchestration ----------------------------------------
extern "C" void kernel_launch(void* const* d_in, const int* in_sizes, int n_in,
                              void* d_out, int out_size) {
    const int*   x       = (const int*)d_in[0];
    const float* embed   = (const float*)d_in[1];
    const float* W_mix   = (const float*)d_in[2];
    const float* b_mix   = (const float*)d_in[3];
    const float* W_in    = (const float*)d_in[4];
    const float* b_in    = (const float*)d_in[5];
    const float* W_link  = (const float*)d_in[6];
    const float* b_link  = (const float*)d_in[7];
    const float* W_ih    = (const float*)d_in[8];
    const float* b_ih    = (const float*)d_in[9];
    const float* W_hh    = (const float*)d_in[10];
    const float* b_hh    = (const float*)d_in[11];
    const float* W_gate  = (const float*)d_in[12];
    const float* b_gate  = (const float*)d_in[13];
    const float* phase   = (const float*)d_in[14];
    const float* pgain   = (const float*)d_in[15];
    const float* W_delta = (const float*)d_in[16];
    const float* b_delta = (const float*)d_in[17];
    const float* decay   = (const float*)d_in[18];
    const float* W_out   = (const float*)d_in[19];
    const float* b_out   = (const float*)d_in[20];

    float *cat, *summary, *shared, *f0, *feats, *gi, *gh, *upd, *gate, *hsA, *hsB;
    cudaGetSymbolAddress((void**)&cat,     g_cat);
    cudaGetSymbolAddress((void**)&summary, g_summary);
    cudaGetSymbolAddress((void**)&shared,  g_shared);
    cudaGetSymbolAddress((void**)&f0,      g_f0);
    cudaGetSymbolAddress((void**)&feats,   g_feats);
    cudaGetSymbolAddress((void**)&gi,      g_gi);
    cudaGetSymbolAddress((void**)&gh,      g_gh);
    cudaGetSymbolAddress((void**)&upd,     g_upd);
    cudaGetSymbolAddress((void**)&gate,    g_gate);
    cudaGetSymbolAddress((void**)&hsA,     g_hsA);
    cudaGetSymbolAddress((void**)&hsB,     g_hsB);

    const long long BW  = (long long)Bb*Ww;
    const long long B3W = (long long)Bb*3*Ww;
    const float invs = 0.35355339059327373f;   // 1/sqrt(S)

    // encode -> cat
    encode_kernel<<<Bb, 128>>>(x, embed);

    // summary = tanh(cat @ W_mix^T + b_mix)
    {
        GemmArgs a{};
        a.A = cat; a.lda = 3*Ww; a.aBatch = 0; a.aRot = 0;
        a.Bt = W_mix; a.ldb = 3*Ww; a.bBatch = 0;
        a.bias = b_mix; a.biasBatch = 0;
        a.D = nullptr; a.gate = nullptr;
        a.C = summary; a.ldc = Ww; a.cBatch = 0;
        a.K = 3*Ww; a.act = 1; a.scale = 1.f;
        sgemm<<<dim3(Ww/128, Bb/128, 1), 256>>>(a);
    }
    post_summary<<<(Bb*Ww)/256, 256>>>();
    zero_kernel<<<(Ss*Bb*Ww)/256, 256>>>(hsA);

    float* hsCur = hsA;
    float* hsNxt = hsB;

    for (int t = 0; t < NSTEPS; ++t) {
        // f0[s] = tanh(shared @ W_in[s]^T + b_in[s])
        {
            GemmArgs a{};
            a.A = shared; a.lda = 2*Ww; a.aBatch = 0; a.aRot = 0;
            a.Bt = W_in; a.ldb = 2*Ww; a.bBatch = (long long)Ww*2*Ww;
            a.bias = b_in; a.biasBatch = Ww;
            a.D = nullptr; a.gate = nullptr;
            a.C = f0; a.ldc = Ww; a.cBatch = BW;
            a.K = 2*Ww; a.act = 1; a.scale = 1.f;
            sgemm<<<dim3(Ww/128, Bb/128, Ss), 256>>>(a);
        }
        // feats[s] = tanh(f0[s] + f0[(s-1)%S] @ W_link[s]^T + b_link[s])
        {
            GemmArgs a{};
            a.A = f0; a.lda = Ww; a.aBatch = BW; a.aRot = 1;
            a.Bt = W_link; a.ldb = Ww; a.bBatch = (long long)Ww*Ww;
            a.bias = b_link; a.biasBatch = Ww;
            a.D = f0; a.ldd = Ww; a.dBatch = BW;
            a.gate = nullptr;
            a.C = feats; a.ldc = Ww; a.cBatch = BW;
            a.K = Ww; a.act = 1; a.scale = 1.f;
            sgemm<<<dim3(Ww/128, Bb/128, Ss), 256>>>(a);
        }
        // gi[s] = feats[s] @ W_ih[s]^T + b_ih[s]
        {
            GemmArgs a{};
            a.A = feats; a.lda = Ww; a.aBatch = BW; a.aRot = 0;
            a.Bt = W_ih; a.ldb = Ww; a.bBatch = (long long)3*Ww*Ww;
            a.bias = b_ih; a.biasBatch = 3*Ww;
            a.D = nullptr; a.gate = nullptr;
            a.C = gi; a.ldc = 3*Ww; a.cBatch = B3W;
            a.K = Ww; a.act = 0; a.scale = 1.f;
            sgemm<<<dim3(3*Ww/128, Bb/128, Ss), 256>>>(a);
        }
        // gh[s] = hs[s] @ W_hh[s]^T + b_hh[s]
        {
            GemmArgs a{};
            a.A = hsCur; a.lda = Ww; a.aBatch = BW; a.aRot = 0;
            a.Bt = W_hh; a.ldb = Ww; a.bBatch = (long long)3*Ww*Ww;
            a.bias = b_hh; a.biasBatch = 3*Ww;
            a.D = nullptr; a.gate = nullptr;
            a.C = gh; a.ldc = 3*Ww; a.cBatch = B3W;
            a.K = Ww; a.act = 0; a.scale = 1.f;
            sgemm<<<dim3(3*Ww/128, Bb/128, Ss), 256>>>(a);
        }
        // GRU -> hsNxt
        gru_combine<<<(Ss*Bb*Ww)/256, 256>>>(hsCur, hsNxt);
        // gate + prism feat2 (into g_f0)
        prism_gate<<<dim3(Bb, Ss), 128>>>(hsNxt, W_gate, b_gate, phase, pgain);
        // upd[s] = gate[b,s] * tanh(feat2[s] @ W_delta[s]^T + b_delta[s]) * invs
        {
            GemmArgs a{};
            a.A = f0; a.lda = Ww; a.aBatch = BW; a.aRot = 0;
            a.Bt = W_delta; a.ldb = Ww; a.bBatch = (long long)Ww*Ww;
            a.bias = b_delta; a.biasBatch = Ww;
            a.D = nullptr;
            a.gate = gate;
            a.C = upd; a.ldc = Ww; a.cBatch = BW;
            a.K = Ww; a.act = 1; a.scale = invs;
            sgemm<<<dim3(Ww/128, Bb/128, Ss), 256>>>(a);
        }
        // h = tanh(h*decay + sum_s upd[s]); refresh shared[:, :W]
        h_update<<<(Bb*Ww)/256, 256>>>(decay);

        float* tmp = hsCur; hsCur = hsNxt; hsNxt = tmp;
    }

    out_proj<<<Bb, dim3(32, NLABEL)>>>(W_out, b_out, (float*)d_out);
}